// round 1
// baseline (speedup 1.0000x reference)
#include <cuda_runtime.h>
#include <cuda_bf16.h>
#include <math.h>

// ---------------------------------------------------------------------------
// Problem constants
// ---------------------------------------------------------------------------
#define B 4
#define SEQ 2048
#define DIM 512
#define NH 8
#define DH 64
#define MLP_DIM 2048
#define INNER (NH * DH)          // 512
#define QKV3 (3 * INNER)         // 1536
#define TOK (B * SEQ)            // 8192
#define DEPTH 4
#define ATT_SCALE 0.125f         // DH^-0.5 = 1/8

// ---------------------------------------------------------------------------
// Scratch buffers (device globals — no allocation allowed)
// ---------------------------------------------------------------------------
__device__ float g_h  [TOK * DIM];      // layernorm output
__device__ float g_qkv[TOK * QKV3];     // qkv projections
__device__ float g_att[TOK * INNER];    // attention output
__device__ float g_ff [TOK * MLP_DIM];  // mlp hidden
__device__ float g_x  [TOK * DIM];      // running residual stream

// ---------------------------------------------------------------------------
// LayerNorm: one block per row (512 elems), 128 threads x 4 elems
// ---------------------------------------------------------------------------
__global__ void ln_kernel(const float* __restrict__ x,
                          const float* __restrict__ g,
                          const float* __restrict__ b,
                          float* __restrict__ out)
{
    const int row = blockIdx.x;
    const int t = threadIdx.x;
    const float* xr = x + (size_t)row * DIM;
    float v[4];
    float s = 0.f;
#pragma unroll
    for (int i = 0; i < 4; i++) { v[i] = xr[t + i * 128]; s += v[i]; }

    __shared__ float red[4];
    // warp reduce
#pragma unroll
    for (int o = 16; o > 0; o >>= 1) s += __shfl_xor_sync(0xffffffffu, s, o);
    if ((t & 31) == 0) red[t >> 5] = s;
    __syncthreads();
    float tot = red[0] + red[1] + red[2] + red[3];
    const float mean = tot * (1.0f / DIM);

    float ss = 0.f;
#pragma unroll
    for (int i = 0; i < 4; i++) { float d = v[i] - mean; ss += d * d; }
#pragma unroll
    for (int o = 16; o > 0; o >>= 1) ss += __shfl_xor_sync(0xffffffffu, ss, o);
    __syncthreads();
    if ((t & 31) == 0) red[t >> 5] = ss;
    __syncthreads();
    float var = (red[0] + red[1] + red[2] + red[3]) * (1.0f / DIM);
    const float rinv = rsqrtf(var + 1e-5f);

    float* orow = out + (size_t)row * DIM;
#pragma unroll
    for (int i = 0; i < 4; i++) {
        int c = t + i * 128;
        orow[c] = (v[i] - mean) * rinv * g[c] + b[c];
    }
}

// ---------------------------------------------------------------------------
// Generic tiled fp32 GEMM: C[M,N] = epilogue(A[M,K] @ W[K,N] + bias (+res))
// BM=BN=64, BK=16, 256 threads, 4x4 microtile per thread.
// ---------------------------------------------------------------------------
__device__ __forceinline__ float gelu_exact(float x) {
    return 0.5f * x * (1.0f + erff(x * 0.70710678118654752f));
}

template<bool DO_GELU, bool DO_RES>
__global__ __launch_bounds__(256)
void gemm_kernel(const float* __restrict__ A, const float* __restrict__ W,
                 const float* __restrict__ bias, const float* __restrict__ res,
                 float* __restrict__ C, int M, int K, int N)
{
    constexpr int BM = 64, BN = 64, BK = 16;
    __shared__ float As[BK][BM + 4];   // +4 pad: avoid transpose-store conflicts
    __shared__ float Bs[BK][BN];

    const int tid = threadIdx.x;
    const int tx = tid & 15;
    const int ty = tid >> 4;
    const int m0 = blockIdx.y * BM;
    const int n0 = blockIdx.x * BN;

    float acc[4][4] = {};

    for (int k0 = 0; k0 < K; k0 += BK) {
        // Load A tile (transposed into As[k][m])
#pragma unroll
        for (int i = 0; i < 4; i++) {
            int idx = tid + i * 256;                 // 0..1023
            int kl = idx & (BK - 1);
            int ml = idx >> 4;
            As[kl][ml] = A[(size_t)(m0 + ml) * K + k0 + kl];
        }
        // Load B tile
#pragma unroll
        for (int i = 0; i < 4; i++) {
            int idx = tid + i * 256;
            int kl = idx >> 6;
            int nl = idx & 63;
            Bs[kl][nl] = W[(size_t)(k0 + kl) * N + n0 + nl];
        }
        __syncthreads();
#pragma unroll
        for (int kk = 0; kk < BK; kk++) {
            float4 av = *reinterpret_cast<const float4*>(&As[kk][ty * 4]);
            float4 bv = *reinterpret_cast<const float4*>(&Bs[kk][tx * 4]);
            float a[4] = {av.x, av.y, av.z, av.w};
            float bb[4] = {bv.x, bv.y, bv.z, bv.w};
#pragma unroll
            for (int i = 0; i < 4; i++)
#pragma unroll
                for (int j = 0; j < 4; j++)
                    acc[i][j] += a[i] * bb[j];
        }
        __syncthreads();
    }

    // Epilogue
#pragma unroll
    for (int i = 0; i < 4; i++) {
        int m = m0 + ty * 4 + i;
#pragma unroll
        for (int j = 0; j < 4; j++) {
            int n = n0 + tx * 4 + j;
            float v = acc[i][j];
            if (bias) v += bias[n];
            if (DO_GELU) v = gelu_exact(v);
            if (DO_RES)  v += res[(size_t)m * N + n];
            C[(size_t)m * N + n] = v;
        }
    }
}

// ---------------------------------------------------------------------------
// Attention: flash-style. Grid (SEQ/128, NH, B), 128 threads, 1 thread = 1
// query row. K/V staged in shared 64-row tiles; online softmax in 16-key
// chunks. qkv layout: [b, n, 3*INNER] with q|k|v thirds, head-major inside.
// ---------------------------------------------------------------------------
__global__ __launch_bounds__(128)
void attn_kernel(const float* __restrict__ qkv, float* __restrict__ out)
{
    const int bb = blockIdx.z;
    const int h  = blockIdx.y;
    const int row = blockIdx.x * 128 + threadIdx.x;
    const size_t base = (size_t)bb * SEQ * QKV3;

    __shared__ float Ksh[64][64];
    __shared__ float Vsh[64][64];

    // Load this thread's q row (scale folded in)
    float q[DH];
    const float* qr = qkv + base + (size_t)row * QKV3 + h * DH;
#pragma unroll
    for (int d = 0; d < DH; d++) q[d] = qr[d] * ATT_SCALE;

    float o[DH];
#pragma unroll
    for (int d = 0; d < DH; d++) o[d] = 0.f;
    float mx = -1e30f, l = 0.f;

    for (int kv0 = 0; kv0 < SEQ; kv0 += 64) {
        __syncthreads();   // protect previous iteration's reads
        // Cooperative tile load: conflict-free scalar, coalesced global
        const float* kbase = qkv + base + (size_t)kv0 * QKV3 + INNER + h * DH;
        const float* vbase = qkv + base + (size_t)kv0 * QKV3 + 2 * INNER + h * DH;
#pragma unroll
        for (int i = 0; i < 32; i++) {
            int idx = threadIdx.x + i * 128;   // 0..4095
            int j = idx >> 6;
            int d = idx & 63;
            Ksh[j][d] = kbase[(size_t)j * QKV3 + d];
            Vsh[j][d] = vbase[(size_t)j * QKV3 + d];
        }
        __syncthreads();

        // 4 chunks of 16 keys
#pragma unroll 1
        for (int jc = 0; jc < 64; jc += 16) {
            float s[16];
#pragma unroll
            for (int j = 0; j < 16; j++) {
                float acc = 0.f;
#pragma unroll
                for (int d = 0; d < DH; d++) acc += q[d] * Ksh[jc + j][d];
                s[j] = acc;
            }
            float mt = mx;
#pragma unroll
            for (int j = 0; j < 16; j++) mt = fmaxf(mt, s[j]);
            float scale = __expf(mx - mt);
            l *= scale;
#pragma unroll
            for (int d = 0; d < DH; d++) o[d] *= scale;
#pragma unroll
            for (int j = 0; j < 16; j++) {
                float p = __expf(s[j] - mt);
                l += p;
#pragma unroll
                for (int d = 0; d < DH; d++) o[d] += p * Vsh[jc + j][d];
            }
            mx = mt;
        }
    }

    // Write out in [b, n, h*DH + d] layout (== [token, INNER])
    float rinv = 1.0f / l;
    float* orow = out + ((size_t)bb * SEQ + row) * INNER + h * DH;
#pragma unroll
    for (int d = 0; d < DH; d++) orow[d] = o[d] * rinv;
}

// ---------------------------------------------------------------------------
// Host orchestration
// ---------------------------------------------------------------------------
extern "C" void kernel_launch(void* const* d_in, const int* in_sizes, int n_in,
                              void* d_out, int out_size)
{
    const float* x     = (const float*)d_in[0];
    const float* Wqkv  = (const float*)d_in[1];
    const float* Wo    = (const float*)d_in[2];
    const float* bo    = (const float*)d_in[3];
    const float* ln1_g = (const float*)d_in[4];
    const float* ln1_b = (const float*)d_in[5];
    const float* W1    = (const float*)d_in[6];
    const float* b1    = (const float*)d_in[7];
    const float* W2    = (const float*)d_in[8];
    const float* b2    = (const float*)d_in[9];
    const float* ln2_g = (const float*)d_in[10];
    const float* ln2_b = (const float*)d_in[11];
    const float* lnf_g = (const float*)d_in[12];
    const float* lnf_b = (const float*)d_in[13];

    float *h, *qkv, *att, *ff, *xb;
    cudaGetSymbolAddress((void**)&h,   g_h);
    cudaGetSymbolAddress((void**)&qkv, g_qkv);
    cudaGetSymbolAddress((void**)&att, g_att);
    cudaGetSymbolAddress((void**)&ff,  g_ff);
    cudaGetSymbolAddress((void**)&xb,  g_x);

    const float* xs = x;   // layer 0 reads the input directly
    for (int L = 0; L < DEPTH; L++) {
        // 1) ln1
        ln_kernel<<<TOK, 128>>>(xs, ln1_g + L * DIM, ln1_b + L * DIM, h);
        // 2) qkv = h @ Wqkv (no bias)
        gemm_kernel<false, false><<<dim3(QKV3 / 64, TOK / 64), 256>>>(
            h, Wqkv + (size_t)L * DIM * QKV3, nullptr, nullptr, qkv,
            TOK, DIM, QKV3);
        // 3) attention
        attn_kernel<<<dim3(SEQ / 128, NH, B), 128>>>(qkv, att);
        // 4) x = xs + att @ Wo + bo
        gemm_kernel<false, true><<<dim3(DIM / 64, TOK / 64), 256>>>(
            att, Wo + (size_t)L * INNER * DIM, bo + L * DIM, xs, xb,
            TOK, INNER, DIM);
        // 5) ln2
        ln_kernel<<<TOK, 128>>>(xb, ln2_g + L * DIM, ln2_b + L * DIM, h);
        // 6) ff = gelu(h @ W1 + b1)
        gemm_kernel<true, false><<<dim3(MLP_DIM / 64, TOK / 64), 256>>>(
            h, W1 + (size_t)L * DIM * MLP_DIM, b1 + L * MLP_DIM, nullptr, ff,
            TOK, DIM, MLP_DIM);
        // 7) x = x + ff @ W2 + b2  (in-place residual: each elem read once
        //    by the same thread that writes it)
        gemm_kernel<false, true><<<dim3(DIM / 64, TOK / 64), 256>>>(
            ff, W2 + (size_t)L * MLP_DIM * DIM, b2 + L * DIM, xb, xb,
            TOK, MLP_DIM, DIM);
        xs = xb;
    }
    // final layernorm -> d_out
    ln_kernel<<<TOK, 128>>>(xb, lnf_g, lnf_b, (float*)d_out);
}

// round 4
// speedup vs baseline: 1.2540x; 1.2540x over previous
#include <cuda_runtime.h>
#include <cuda_bf16.h>
#include <mma.h>
#include <math.h>
#include <cstdint>

using namespace nvcuda;

// ---------------------------------------------------------------------------
// Problem constants
// ---------------------------------------------------------------------------
#define B 4
#define SEQ 2048
#define DIM 512
#define NH 8
#define DH 64
#define MLP_DIM 2048
#define INNER (NH * DH)          // 512
#define QKV3 (3 * INNER)         // 1536
#define TOK (B * SEQ)            // 8192
#define DEPTH 4
#define ATT_SCALE 0.125f         // DH^-0.5

// ---------------------------------------------------------------------------
// Scratch buffers (device globals — no allocation allowed)
// ---------------------------------------------------------------------------
__device__ float g_h  [TOK * DIM];
__device__ float g_qkv[TOK * QKV3];
__device__ float g_att[TOK * INNER];
__device__ float g_ff [TOK * MLP_DIM];
__device__ float g_x  [TOK * DIM];

// ---------------------------------------------------------------------------
// LayerNorm: one block per row (512 elems), 128 threads x 4 elems
// ---------------------------------------------------------------------------
__global__ void ln_kernel(const float* __restrict__ x,
                          const float* __restrict__ g,
                          const float* __restrict__ b,
                          float* __restrict__ out)
{
    const int row = blockIdx.x;
    const int t = threadIdx.x;
    const float* xr = x + (size_t)row * DIM;
    float v[4];
    float s = 0.f;
#pragma unroll
    for (int i = 0; i < 4; i++) { v[i] = xr[t + i * 128]; s += v[i]; }

    __shared__ float red[4];
#pragma unroll
    for (int o = 16; o > 0; o >>= 1) s += __shfl_xor_sync(0xffffffffu, s, o);
    if ((t & 31) == 0) red[t >> 5] = s;
    __syncthreads();
    float tot = red[0] + red[1] + red[2] + red[3];
    const float mean = tot * (1.0f / DIM);

    float ss = 0.f;
#pragma unroll
    for (int i = 0; i < 4; i++) { float d = v[i] - mean; ss += d * d; }
#pragma unroll
    for (int o = 16; o > 0; o >>= 1) ss += __shfl_xor_sync(0xffffffffu, ss, o);
    __syncthreads();
    if ((t & 31) == 0) red[t >> 5] = ss;
    __syncthreads();
    float var = (red[0] + red[1] + red[2] + red[3]) * (1.0f / DIM);
    const float rinv = rsqrtf(var + 1e-5f);

    float* orow = out + (size_t)row * DIM;
#pragma unroll
    for (int i = 0; i < 4; i++) {
        int c = t + i * 128;
        orow[c] = (v[i] - mean) * rinv * g[c] + b[c];
    }
}

// ---------------------------------------------------------------------------
// tf32 tensor-core GEMM: C[M,N] = epi(A[M,K] @ W[K,N] + bias (+res))
// BM=128, BN=128, BK=32, 256 threads, 8 warps (4x2), warp tile 32x64.
// cp.async double buffering; epilogue staged through shared.
// ---------------------------------------------------------------------------
#define GBM 128
#define GBN 128
#define GBK 32
#define APAD 8
#define BPAD 8
#define ALD (GBK + APAD)   // 40 floats  -> 160B row stride (32B aligned)
#define BLD (GBN + BPAD)   // 136 floats -> 544B row stride (32B aligned)
#define GEMM_SMEM_BYTES ((2 * GBM * ALD + 2 * GBK * BLD) * 4)

__device__ __forceinline__ void cpasync16(void* smem, const void* gmem) {
    unsigned int s = (unsigned int)__cvta_generic_to_shared(smem);
    asm volatile("cp.async.ca.shared.global [%0], [%1], 16;\n" :: "r"(s), "l"(gmem));
}

__device__ __forceinline__ float gelu_exact(float x) {
    return 0.5f * x * (1.0f + erff(x * 0.70710678118654752f));
}

template<bool DO_GELU, bool DO_RES>
__global__ __launch_bounds__(256)
void gemm_tf32(const float* __restrict__ A, const float* __restrict__ W,
               const float* __restrict__ bias, const float* __restrict__ res,
               float* __restrict__ C, int M, int K, int N)
{
    extern __shared__ float smem[];
    float (*As)[GBM][ALD] = reinterpret_cast<float(*)[GBM][ALD]>(smem);
    float (*Bs)[GBK][BLD] = reinterpret_cast<float(*)[GBK][BLD]>(smem + 2 * GBM * ALD);
    float (*Cs)[BLD]      = reinterpret_cast<float(*)[BLD]>(smem);   // epilogue alias

    const int tid = threadIdx.x;
    const int warp = tid >> 5;
    const int wm = warp >> 1;      // 0..3 : 32-row slab
    const int wn = warp & 1;       // 0..1 : 64-col slab
    const int m0 = blockIdx.y * GBM;
    const int n0 = blockIdx.x * GBN;

    wmma::fragment<wmma::accumulator, 16, 16, 8, float> c[2][4];
#pragma unroll
    for (int i = 0; i < 2; i++)
#pragma unroll
        for (int j = 0; j < 4; j++) wmma::fill_fragment(c[i][j], 0.0f);

    const int KT = K / GBK;

    auto issue = [&](int kt, int s) {
        const int k0 = kt * GBK;
#pragma unroll
        for (int i = 0; i < 4; i++) {                 // A: 1024 float4
            int idx = tid + i * 256;
            int r = idx >> 3, c4 = (idx & 7) * 4;
            cpasync16(&As[s][r][c4], &A[(size_t)(m0 + r) * K + k0 + c4]);
        }
#pragma unroll
        for (int i = 0; i < 4; i++) {                 // B: 1024 float4
            int idx = tid + i * 256;
            int r = idx >> 5, c4 = (idx & 31) * 4;
            cpasync16(&Bs[s][r][c4], &W[(size_t)(k0 + r) * N + n0 + c4]);
        }
        asm volatile("cp.async.commit_group;\n");
    };

    issue(0, 0);
    for (int kt = 0; kt < KT; kt++) {
        const int s = kt & 1;
        if (kt + 1 < KT) issue(kt + 1, s ^ 1);
        else             asm volatile("cp.async.commit_group;\n");
        asm volatile("cp.async.wait_group 1;\n");
        __syncthreads();

#pragma unroll
        for (int kk = 0; kk < GBK; kk += 8) {
            wmma::fragment<wmma::matrix_a, 16, 16, 8, wmma::precision::tf32, wmma::row_major> a[2];
            wmma::fragment<wmma::matrix_b, 16, 16, 8, wmma::precision::tf32, wmma::row_major> b[4];
#pragma unroll
            for (int i = 0; i < 2; i++) {
                wmma::load_matrix_sync(a[i], &As[s][wm * 32 + i * 16][kk], ALD);
#pragma unroll
                for (int t = 0; t < a[i].num_elements; t++)
                    a[i].x[t] = wmma::__float_to_tf32(a[i].x[t]);
            }
#pragma unroll
            for (int j = 0; j < 4; j++) {
                wmma::load_matrix_sync(b[j], &Bs[s][kk][wn * 64 + j * 16], BLD);
#pragma unroll
                for (int t = 0; t < b[j].num_elements; t++)
                    b[j].x[t] = wmma::__float_to_tf32(b[j].x[t]);
            }
#pragma unroll
            for (int i = 0; i < 2; i++)
#pragma unroll
                for (int j = 0; j < 4; j++)
                    wmma::mma_sync(c[i][j], a[i], b[j], c[i][j]);
        }
        __syncthreads();
    }

    // Epilogue: stage through shared for coalesced fused writes
#pragma unroll
    for (int i = 0; i < 2; i++)
#pragma unroll
        for (int j = 0; j < 4; j++)
            wmma::store_matrix_sync(&Cs[wm * 32 + i * 16][wn * 64 + j * 16],
                                    c[i][j], BLD, wmma::mem_row_major);
    __syncthreads();

#pragma unroll
    for (int i = 0; i < 16; i++) {
        int idx = tid + i * 256;          // 0..4095 float4 groups
        int r = idx >> 5;
        int c4 = (idx & 31) * 4;
        float4 v = *reinterpret_cast<float4*>(&Cs[r][c4]);
        if (bias) {
            float4 bv = *reinterpret_cast<const float4*>(&bias[n0 + c4]);
            v.x += bv.x; v.y += bv.y; v.z += bv.z; v.w += bv.w;
        }
        if (DO_GELU) {
            v.x = gelu_exact(v.x); v.y = gelu_exact(v.y);
            v.z = gelu_exact(v.z); v.w = gelu_exact(v.w);
        }
        if (DO_RES) {
            float4 rv = *reinterpret_cast<const float4*>(&res[(size_t)(m0 + r) * N + n0 + c4]);
            v.x += rv.x; v.y += rv.y; v.z += rv.z; v.w += rv.w;
        }
        *reinterpret_cast<float4*>(&C[(size_t)(m0 + r) * N + n0 + c4]) = v;
    }
}

// ---------------------------------------------------------------------------
// Attention: flash-style, fp32 (unchanged from R1 — correct, fma-bound)
// ---------------------------------------------------------------------------
__global__ __launch_bounds__(128)
void attn_kernel(const float* __restrict__ qkv, float* __restrict__ out)
{
    const int bb = blockIdx.z;
    const int h  = blockIdx.y;
    const int row = blockIdx.x * 128 + threadIdx.x;
    const size_t base = (size_t)bb * SEQ * QKV3;

    __shared__ float Ksh[64][64];
    __shared__ float Vsh[64][64];

    float q[DH];
    const float* qr = qkv + base + (size_t)row * QKV3 + h * DH;
#pragma unroll
    for (int d = 0; d < DH; d++) q[d] = qr[d] * ATT_SCALE;

    float o[DH];
#pragma unroll
    for (int d = 0; d < DH; d++) o[d] = 0.f;
    float mx = -1e30f, l = 0.f;

    for (int kv0 = 0; kv0 < SEQ; kv0 += 64) {
        __syncthreads();
        const float* kbase = qkv + base + (size_t)kv0 * QKV3 + INNER + h * DH;
        const float* vbase = qkv + base + (size_t)kv0 * QKV3 + 2 * INNER + h * DH;
#pragma unroll
        for (int i = 0; i < 32; i++) {
            int idx = threadIdx.x + i * 128;
            int j = idx >> 6;
            int d = idx & 63;
            Ksh[j][d] = kbase[(size_t)j * QKV3 + d];
            Vsh[j][d] = vbase[(size_t)j * QKV3 + d];
        }
        __syncthreads();

#pragma unroll 1
        for (int jc = 0; jc < 64; jc += 16) {
            float s[16];
#pragma unroll
            for (int j = 0; j < 16; j++) {
                float acc = 0.f;
#pragma unroll
                for (int d = 0; d < DH; d++) acc += q[d] * Ksh[jc + j][d];
                s[j] = acc;
            }
            float mt = mx;
#pragma unroll
            for (int j = 0; j < 16; j++) mt = fmaxf(mt, s[j]);
            float scale = __expf(mx - mt);
            l *= scale;
#pragma unroll
            for (int d = 0; d < DH; d++) o[d] *= scale;
#pragma unroll
            for (int j = 0; j < 16; j++) {
                float p = __expf(s[j] - mt);
                l += p;
#pragma unroll
                for (int d = 0; d < DH; d++) o[d] += p * Vsh[jc + j][d];
            }
            mx = mt;
        }
    }

    float rinv = 1.0f / l;
    float* orow = out + ((size_t)bb * SEQ + row) * INNER + h * DH;
#pragma unroll
    for (int d = 0; d < DH; d++) orow[d] = o[d] * rinv;
}

// ---------------------------------------------------------------------------
// Host orchestration
// ---------------------------------------------------------------------------
extern "C" void kernel_launch(void* const* d_in, const int* in_sizes, int n_in,
                              void* d_out, int out_size)
{
    const float* x     = (const float*)d_in[0];
    const float* Wqkv  = (const float*)d_in[1];
    const float* Wo    = (const float*)d_in[2];
    const float* bo    = (const float*)d_in[3];
    const float* ln1_g = (const float*)d_in[4];
    const float* ln1_b = (const float*)d_in[5];
    const float* W1    = (const float*)d_in[6];
    const float* b1    = (const float*)d_in[7];
    const float* W2    = (const float*)d_in[8];
    const float* b2    = (const float*)d_in[9];
    const float* ln2_g = (const float*)d_in[10];
    const float* ln2_b = (const float*)d_in[11];
    const float* lnf_g = (const float*)d_in[12];
    const float* lnf_b = (const float*)d_in[13];

    float *h, *qkv, *att, *ff, *xb;
    cudaGetSymbolAddress((void**)&h,   g_h);
    cudaGetSymbolAddress((void**)&qkv, g_qkv);
    cudaGetSymbolAddress((void**)&att, g_att);
    cudaGetSymbolAddress((void**)&ff,  g_ff);
    cudaGetSymbolAddress((void**)&xb,  g_x);

    cudaFuncSetAttribute(gemm_tf32<false, false>,
                         cudaFuncAttributeMaxDynamicSharedMemorySize, GEMM_SMEM_BYTES);
    cudaFuncSetAttribute(gemm_tf32<false, true>,
                         cudaFuncAttributeMaxDynamicSharedMemorySize, GEMM_SMEM_BYTES);
    cudaFuncSetAttribute(gemm_tf32<true, false>,
                         cudaFuncAttributeMaxDynamicSharedMemorySize, GEMM_SMEM_BYTES);

    const float* xs = x;
    for (int L = 0; L < DEPTH; L++) {
        ln_kernel<<<TOK, 128>>>(xs, ln1_g + L * DIM, ln1_b + L * DIM, h);
        gemm_tf32<false, false><<<dim3(QKV3 / GBN, TOK / GBM), 256, GEMM_SMEM_BYTES>>>(
            h, Wqkv + (size_t)L * DIM * QKV3, nullptr, nullptr, qkv,
            TOK, DIM, QKV3);
        attn_kernel<<<dim3(SEQ / 128, NH, B), 128>>>(qkv, att);
        gemm_tf32<false, true><<<dim3(DIM / GBN, TOK / GBM), 256, GEMM_SMEM_BYTES>>>(
            att, Wo + (size_t)L * INNER * DIM, bo + L * DIM, xs, xb,
            TOK, INNER, DIM);
        ln_kernel<<<TOK, 128>>>(xb, ln2_g + L * DIM, ln2_b + L * DIM, h);
        gemm_tf32<true, false><<<dim3(MLP_DIM / GBN, TOK / GBM), 256, GEMM_SMEM_BYTES>>>(
            h, W1 + (size_t)L * DIM * MLP_DIM, b1 + L * MLP_DIM, nullptr, ff,
            TOK, DIM, MLP_DIM);
        gemm_tf32<false, true><<<dim3(DIM / GBN, TOK / GBM), 256, GEMM_SMEM_BYTES>>>(
            ff, W2 + (size_t)L * MLP_DIM * DIM, b2 + L * DIM, xb, xb,
            TOK, MLP_DIM, DIM);
        xs = xb;
    }
    ln_kernel<<<TOK, 128>>>(xb, lnf_g, lnf_b, (float*)d_out);
}